// round 12
// baseline (speedup 1.0000x reference)
#include <cuda_runtime.h>
#include <cuda_fp16.h>
#include <cstdint>

#define NB    4
#define NS    64
#define NC    8
#define NR    64
#define NPIX  65536
#define NSAMP 12
#define HID   64
#define COUT  8

// ---------------- dynamic smem layout ----------------
#define OFF_A0    0            // 18432 (128 x 64 fp16, pitch 144)
#define OFF_A1    18432        // 18432   (A0+A1 = 36864 reused as h2m f32[128][72])
#define OFF_W     36864        // 64*144 = 9216
#define OFF_SIDX  46080        // int[12][128] = 6144 (fused g_Ah index)
#define OFF_SPXY  52224        // uint2[128] = 1024  ((px,px),(py,py) half2 pairs)
#define OFF_SAB   53248        // int[128] = 512
#define OFF_B2    53760        // f32[64] = 256
#define OFF_W3    54016        // f32[8][64] = 2048
#define OFF_PART  56576        // f32[128][8] = 4096
#define OFF_RAW   60672        // per-warp staging: 8 warps x 2 bufs x 2048B = 32768
#define SMEM_TOTAL 93440

// g_A as fp16 pairs: [bs(256)][r(64)][h2(32)] uint32 (half2 of h=2*h2, 2*h2+1)
__device__ __align__(16) uint32_t g_Ah[NB * NS * NR * (HID / 2)];

// ---------------- helpers ----------------
__device__ __forceinline__ uint32_t smem_u32(const void* p) {
    uint32_t a;
    asm("{ .reg .u64 t; cvta.to.shared.u64 t, %1; cvt.u32.u64 %0, t; }" : "=r"(a) : "l"(p));
    return a;
}
__device__ __forceinline__ uint32_t packh2(float a, float b) {   // lo=a, hi=b
    uint32_t r;
    asm("cvt.rn.f16x2.f32 %0, %2, %1;" : "=r"(r) : "f"(a), "f"(b));
    return r;
}
__device__ __forceinline__ __half2 u2h(uint32_t u) { __half2 h; *(uint32_t*)&h = u; return h; }
__device__ __forceinline__ uint32_t h2u(__half2 h) { return *(uint32_t*)&h; }
__device__ __forceinline__ __half2 tanh_h2(__half2 x) {
    uint32_t r;
    asm("tanh.approx.f16x2 %0, %1;" : "=r"(r) : "r"(h2u(x)));
    return u2h(r);
}
__device__ __forceinline__ __half2 gelu_h2(__half2 x) {
    const __half2 c1 = __float2half2_rn(0.035677408136300125f);
    const __half2 c0 = __float2half2_rn(0.7978845608028654f);
    const __half2 hf = __float2half2_rn(0.5f);
    __half2 x2 = __hmul2(x, x);
    __half2 t  = __hmul2(x, __hfma2(c1, x2, c0));
    __half2 th = tanh_h2(t);
    __half2 hx = __hmul2(hf, x);
    return __hfma2(hx, th, hx);
}
// epilogue: fp32 argument + wrap, f16x2 tanh (1 MUFU per 2 values)
__device__ __forceinline__ void gelu2_acc(float x0, float x1, float& a0, float& a1) {
    float t0 = x0 * fmaf(0.035677408136300125f, x0 * x0, 0.7978845608028654f);
    float t1 = x1 * fmaf(0.035677408136300125f, x1 * x1, 0.7978845608028654f);
    uint32_t th2;
    asm("tanh.approx.f16x2 %0, %1;" : "=r"(th2) : "r"(packh2(t0, t1)));
    float2 th = __half22float2(u2h(th2));
    float h0 = 0.5f * x0, h1 = 0.5f * x1;
    a0 += fmaf(h0, th.x, h0);
    a1 += fmaf(h1, th.y, h1);
}
__device__ __forceinline__ void ldmx4(uint32_t* r, uint32_t addr) {
    asm volatile("ldmatrix.sync.aligned.m8n8.x4.shared.b16 {%0,%1,%2,%3}, [%4];"
        : "=r"(r[0]), "=r"(r[1]), "=r"(r[2]), "=r"(r[3]) : "r"(addr));
}
__device__ __forceinline__ void mma16816(float* c, const uint32_t* a, uint32_t b0, uint32_t b1) {
    asm volatile("mma.sync.aligned.m16n8k16.row.col.f32.f16.f16.f32 "
        "{%0,%1,%2,%3}, {%4,%5,%6,%7}, {%8,%9}, {%0,%1,%2,%3};"
        : "+f"(c[0]), "+f"(c[1]), "+f"(c[2]), "+f"(c[3])
        : "r"(a[0]), "r"(a[1]), "r"(a[2]), "r"(a[3]), "r"(b0), "r"(b1));
}
__device__ __forceinline__ void cp_async16(uint32_t saddr, const void* gptr) {
    asm volatile("cp.async.cg.shared.global [%0], [%1], 16;" :: "r"(saddr), "l"(gptr));
}
#define CP_COMMIT() asm volatile("cp.async.commit_group;" ::: "memory")
#define CP_WAIT0()  asm volatile("cp.async.wait_group 0;" ::: "memory")

// ---------------- kernel 1: layer-1 constant table (fp16 pairs) ----------------
__global__ void precompute_A(const float* __restrict__ ref,
                             const float* __restrict__ W1,
                             const float* __restrict__ b1) {
    __shared__ float sref[NC][NR];
    __shared__ float sW1[HID][11];
    __shared__ float sb1[HID];
    int bs = blockIdx.x;
    const float* rp = ref + (size_t)bs * NC * NR;
    for (int i = threadIdx.x; i < NC * NR; i += 256) sref[i >> 6][i & 63] = rp[i];
    for (int i = threadIdx.x; i < HID * 11; i += 256) sW1[i / 11][i % 11] = W1[i];
    if (threadIdx.x < HID) sb1[threadIdx.x] = b1[threadIdx.x];
    __syncthreads();
    int h2 = threadIdx.x & 31;
    int rq = threadIdx.x >> 5;
    int h0 = 2 * h2, h1 = 2 * h2 + 1;
    float w00 = sW1[h0][0], w01 = sW1[h1][0];
    float bb0 = sb1[h0],    bb1 = sb1[h1];
    float wc0[8], wc1[8];
    #pragma unroll
    for (int c = 0; c < 8; c++) { wc0[c] = sW1[h0][3 + c]; wc1[c] = sW1[h1][3 + c]; }
    for (int r = rq * 8; r < rq * 8 + 8; r++) {
        float rc   = fmaf((float)r, 2.0f / 63.0f, -1.0f);
        float acc0 = fmaf(w00, rc, bb0);
        float acc1 = fmaf(w01, rc, bb1);
        #pragma unroll
        for (int c = 0; c < 8; c++) {
            float sv = sref[c][r];
            acc0 = fmaf(wc0[c], sv, acc0);
            acc1 = fmaf(wc1[c], sv, acc1);
        }
        g_Ah[((size_t)bs * NR + r) * 32 + h2] = packh2(acc0, acc1);
    }
}

// ---------------- kernel 2: fp16 HMMA + cp.async gather, SMSP-spread pairs ----------------
__global__ void __launch_bounds__(256, 2) mlp_mma_kernel(
    const float* __restrict__ pc,
    const int*   __restrict__ lookup,
    const int*   __restrict__ samp,
    const float* __restrict__ W1,
    const float* __restrict__ W2,
    const float* __restrict__ b2,
    const float* __restrict__ W3,
    const float* __restrict__ b3,
    float*       __restrict__ out)
{
    extern __shared__ __align__(16) char smem[];
    const uint32_t sbase = smem_u32(smem);
    const int tid  = threadIdx.x;
    const int lane = tid & 31;
    const int w    = tid >> 5;
    const int ch   = w & 1;             // pair warps w=2rg, 2rg+1 -> adjacent SMSPs
    const int rg   = w >> 1;            // MMA row group: rows 32rg..32rg+31
    const int r    = tid & 127;         // final-phase pixel id
    const int half = tid >> 7;          // final-phase j-half

    const int tileb = blockIdx.x;       // 0..2047
    const int b     = tileb >> 9;
    const int n0    = (tileb & 511) * 128;

    int*   sidx  = (int*)  (smem + OFF_SIDX);
    uint2* spxy2 = (uint2*)(smem + OFF_SPXY);
    int*   sab   = (int*)  (smem + OFF_SAB);
    float* sb2   = (float*)(smem + OFF_B2);
    float* sW3   = (float*)(smem + OFF_W3);
    float* part  = (float*)(smem + OFF_PART);

    // ---- prologue phase A ----
    if (tid < 128) {
        float px = pc[n0 + tid];
        float py = pc[NPIX + n0 + tid];
        spxy2[tid] = make_uint2(packh2(px, px), packh2(py, py));
        int sub  = lookup[n0 + tid];
        sab[tid] = ((b << 6) + sub) << 11;   // uint32 index into g_Ah
    }
    // W2 -> fp16 tile [j][k], pitch 144
    for (int i = tid; i < HID * HID; i += 256) {
        int j = i >> 6, k = i & 63;
        *(__half*)(smem + OFF_W + j * 144 + 2 * k) = __float2half_rn(W2[i]);
    }
    if (tid < HID) sb2[tid] = b2[tid];
    for (int i = tid; i < COUT * HID; i += 256) sW3[i] = W3[i];
    __syncthreads();

    // ---- prologue phase B: fused gather indices (sab + idx*32) ----
    for (int i = tid; i < 128 * NSAMP; i += 256) {
        int rr = i / NSAMP, ss = i % NSAMP;
        sidx[ss * 128 + rr] = sab[rr] + samp[(size_t)(n0 + rr) * NSAMP + ss] * 32;
    }

    // per-lane W1 coord weights as half2 (h = 2*lane, 2*lane+1)
    const int l2 = lane * 2;
    const __half2 w11h = u2h(packh2(W1[l2 * 11 + 1], W1[(l2 + 1) * 11 + 1]));
    const __half2 w12h = u2h(packh2(W1[l2 * 11 + 2], W1[(l2 + 1) * 11 + 2]));

    // W fragments resident in registers for all samples
    const uint32_t b_row  = (uint32_t)((lane & 7) + ((lane >> 4) & 1) * 8);
    const uint32_t b_coff = (uint32_t)(((lane >> 3) & 1) * 16);
    uint32_t Bf[2][4][4];
    #pragma unroll
    for (int nt = 0; nt < 2; nt++)
        #pragma unroll
        for (int ks = 0; ks < 4; ks++)
            ldmx4(Bf[nt][ks],
                  sbase + OFF_W + (uint32_t)(ch * 32 + nt * 16 + b_row) * 144 + b_coff + ks * 32);

    // per-warp epilogue biases in regs
    const int jq = ch * 32 + (lane & 3) * 2;
    float bj0[4], bj1[4];
    #pragma unroll
    for (int nti = 0; nti < 4; nti++) { bj0[nti] = sb2[jq + nti * 8]; bj1[nti] = sb2[jq + nti * 8 + 1]; }

    const uint32_t a_row  = (uint32_t)((lane & 7) + ((lane >> 3) & 1) * 8);
    const uint32_t a_coff = (uint32_t)(((lane >> 4) & 1) * 16);

    __syncthreads();   // sidx ready

    // ---- warp-local h1 build: cp.async stage -> finish ----
    const int p0       = rg * 32 + ch * 16;     // this warp's build rows
    const int sub_row  = lane >> 3;             // 0..3 (4 rows per pass)
    const int chunk16  = (lane & 7) * 16;       // 16B chunk within a 128B row
    const uint32_t raw_base = sbase + OFF_RAW + (uint32_t)w * 4096;

    auto issue_gather = [&](int s, int buf) {   // 4 x cp.async.16B per lane
        uint32_t dst = raw_base + (uint32_t)buf * 2048 + chunk16;
        const int* sidx_s = sidx + s * 128 + p0;
        #pragma unroll
        for (int q = 0; q < 4; q++) {
            int row = sub_row + q * 4;
            int gi  = sidx_s[row];              // 8-lane broadcast LDS.32
            cp_async16(dst + (uint32_t)row * 128,
                       (const char*)g_Ah + (size_t)gi * 4 + chunk16);
        }
        CP_COMMIT();
    };
    auto finish_h1 = [&](int buf, int aoff) {
        const char* rawp = smem + OFF_RAW + w * 4096 + buf * 2048 + lane * 4;
        char* abuf = smem + aoff + lane * 4;
        #pragma unroll
        for (int t = 0; t < 16; t++) {
            int p = p0 + t;
            uint2 pxy = spxy2[p];                           // broadcast LDS.64
            uint32_t av = *(const uint32_t*)(rawp + t * 128); // conflict-free LDS.32
            __half2 pre = __hfma2(w11h, u2h(pxy.x), __hfma2(w12h, u2h(pxy.y), u2h(av)));
            *(uint32_t*)(abuf + p * 144) = h2u(gelu_h2(pre));
        }
    };

    #define PAIR_BAR() asm volatile("bar.sync %0, 64;" :: "r"(rg + 1) : "memory")

    float h2acc[2][4][4];
    #pragma unroll
    for (int mt = 0; mt < 2; mt++)
        #pragma unroll
        for (int nti = 0; nti < 4; nti++)
            #pragma unroll
            for (int i = 0; i < 4; i++) h2acc[mt][nti][i] = 0.0f;

    issue_gather(0, 0);
    CP_WAIT0();
    finish_h1(0, OFF_A0);
    PAIR_BAR();

    for (int s = 0; s < NSAMP; s++) {
        const uint32_t abase = sbase + (s & 1 ? OFF_A1 : OFF_A0);

        // stage next sample's gather; L2 latency rides under MMA + epilogue
        if (s + 1 < NSAMP) issue_gather(s + 1, (s + 1) & 1);

        // ---- MMA: warp (rg,ch) computes rows 32rg..+31 x cols 32ch..+31 ----
        float c[2][4][4];
        #pragma unroll
        for (int mt = 0; mt < 2; mt++)
            #pragma unroll
            for (int nti = 0; nti < 4; nti++) {     // bias-init accumulators
                c[mt][nti][0] = bj0[nti];
                c[mt][nti][1] = bj1[nti];
                c[mt][nti][2] = bj0[nti];
                c[mt][nti][3] = bj1[nti];
            }

        #pragma unroll
        for (int mt = 0; mt < 2; mt++) {
            uint32_t arow = abase + (uint32_t)(rg * 32 + mt * 16 + a_row) * 144 + a_coff;
            #pragma unroll
            for (int ks = 0; ks < 4; ks++) {
                uint32_t af[4];
                ldmx4(af, arow + ks * 32);
                #pragma unroll
                for (int nt = 0; nt < 2; nt++) {
                    mma16816(c[mt][nt * 2 + 0], af, Bf[nt][ks][0], Bf[nt][ks][1]);
                    mma16816(c[mt][nt * 2 + 1], af, Bf[nt][ks][2], Bf[nt][ks][3]);
                }
            }
        }
        // epilogue: fp32 wrap, f16x2 tanh (1 MUFU / 2 values), fp32 accumulate
        #pragma unroll
        for (int mt = 0; mt < 2; mt++)
            #pragma unroll
            for (int nti = 0; nti < 4; nti++) {
                gelu2_acc(c[mt][nti][0], c[mt][nti][1], h2acc[mt][nti][0], h2acc[mt][nti][1]);
                gelu2_acc(c[mt][nti][2], c[mt][nti][3], h2acc[mt][nti][2], h2acc[mt][nti][3]);
            }

        if (s + 1 < NSAMP) {
            CP_WAIT0();
            finish_h1((s + 1) & 1, (s + 1) & 1 ? OFF_A1 : OFF_A0);
        }
        PAIR_BAR();
    }
    __syncthreads();   // all warps done -> safe to reuse A region as h2m

    // ---- h2 mean -> smem [128][72] (reuses A region) ----
    float* h2m = (float*)(smem + OFF_A0);
    {
        const float inv = 1.0f / 12.0f;
        int r0  = rg * 32 + (lane >> 2);
        int col = ch * 32 + (lane & 3) * 2;
        #pragma unroll
        for (int mt = 0; mt < 2; mt++)
            #pragma unroll
            for (int nti = 0; nti < 4; nti++) {
                int row = r0 + mt * 16;
                *(float2*)(h2m + row * 72 + col + nti * 8) =
                    make_float2(h2acc[mt][nti][0] * inv, h2acc[mt][nti][1] * inv);
                *(float2*)(h2m + (row + 8) * 72 + col + nti * 8) =
                    make_float2(h2acc[mt][nti][2] * inv, h2acc[mt][nti][3] * inv);
            }
    }
    __syncthreads();

    // ---- layer 3 (mean folded): thread (r, half) covers j in [32*half, 32*half+32) ----
    {
        float pacc[COUT];
        #pragma unroll
        for (int c = 0; c < COUT; c++) pacc[c] = 0.0f;
        const float* hrow = h2m + r * 72 + half * 32;
        #pragma unroll
        for (int q = 0; q < 8; q++) {
            float4 h4 = *(const float4*)(hrow + q * 4);
            int j = half * 32 + q * 4;
            #pragma unroll
            for (int c = 0; c < COUT; c++) {
                const float* w3r = sW3 + c * HID + j;
                pacc[c] = fmaf(w3r[0], h4.x, pacc[c]);
                pacc[c] = fmaf(w3r[1], h4.y, pacc[c]);
                pacc[c] = fmaf(w3r[2], h4.z, pacc[c]);
                pacc[c] = fmaf(w3r[3], h4.w, pacc[c]);
            }
        }
        if (half == 1) {
            #pragma unroll
            for (int c = 0; c < COUT; c++) part[r * COUT + c] = pacc[c];
        }
        __syncthreads();
        if (half == 0) {
            size_t base = (size_t)b * COUT * NPIX + n0 + r;
            #pragma unroll
            for (int c = 0; c < COUT; c++)
                out[base + (size_t)c * NPIX] = pacc[c] + part[r * COUT + c] + __ldg(b3 + c);
        }
    }
}

// ---------------- launch ----------------
extern "C" void kernel_launch(void* const* d_in, const int* in_sizes, int n_in,
                              void* d_out, int out_size) {
    const float* ref    = (const float*)d_in[0];
    const float* pc     = (const float*)d_in[1];
    const int*   lookup = (const int*)d_in[2];
    const int*   samp   = (const int*)d_in[3];
    const float* W1     = (const float*)d_in[4];
    const float* b1     = (const float*)d_in[5];
    const float* W2     = (const float*)d_in[6];
    const float* b2     = (const float*)d_in[7];
    const float* W3     = (const float*)d_in[8];
    const float* b3     = (const float*)d_in[9];
    float* out = (float*)d_out;

    cudaFuncSetAttribute(mlp_mma_kernel, cudaFuncAttributeMaxDynamicSharedMemorySize, SMEM_TOTAL);

    precompute_A<<<NB * NS, 256>>>(ref, W1, b1);
    mlp_mma_kernel<<<NB * (NPIX / 128), 256, SMEM_TOTAL>>>(
        pc, lookup, samp, W1, W2, b2, W3, b3, out);
}

// round 13
// speedup vs baseline: 1.0564x; 1.0564x over previous
#include <cuda_runtime.h>
#include <cuda_fp16.h>
#include <cstdint>

#define NB    4
#define NS    64
#define NC    8
#define NR    64
#define NPIX  65536
#define NSAMP 12
#define HID   64
#define COUT  8

// ---------------- dynamic smem layout ----------------
#define OFF_A0    0            // 18432 (128 x 64 fp16, pitch 144)
#define OFF_A1    18432        // 18432   (A0+A1 = 36864 reused as h2m f32[128][72])
#define OFF_W     36864        // 64*144 = 9216
#define OFF_SIDX  46080        // int[12][128] = 6144 (fused g_Ah index)
#define OFF_SPXY  52224        // uint2[128] = 1024  ((px,px),(py,py) half2 pairs)
#define OFF_SAB   53248        // int[128] = 512
#define OFF_B2    53760        // f32[64] = 256
#define OFF_W3    54016        // f32[8][64] = 2048
#define OFF_PART  56576        // f32[128][8] = 4096
#define OFF_RAW   60672        // per-warp staging: 8 warps x 2 bufs x 2048B = 32768
#define OFF_CC    93440        // coord term: 128 rows x 32 lanes x 4B = 16384
#define SMEM_TOTAL 109824

// g_A as fp16 pairs: [bs(256)][r(64)][h2(32)] uint32 (half2 of h=2*h2, 2*h2+1)
__device__ __align__(16) uint32_t g_Ah[NB * NS * NR * (HID / 2)];
// W2 as fp16, pitch-144 row layout (ready for direct smem copy)
__device__ __align__(16) uint32_t g_W2h[HID * 36];

// ---------------- helpers ----------------
__device__ __forceinline__ uint32_t smem_u32(const void* p) {
    uint32_t a;
    asm("{ .reg .u64 t; cvta.to.shared.u64 t, %1; cvt.u32.u64 %0, t; }" : "=r"(a) : "l"(p));
    return a;
}
__device__ __forceinline__ uint32_t packh2(float a, float b) {   // lo=a, hi=b
    uint32_t r;
    asm("cvt.rn.f16x2.f32 %0, %2, %1;" : "=r"(r) : "f"(a), "f"(b));
    return r;
}
__device__ __forceinline__ __half2 u2h(uint32_t u) { __half2 h; *(uint32_t*)&h = u; return h; }
__device__ __forceinline__ uint32_t h2u(__half2 h) { return *(uint32_t*)&h; }
__device__ __forceinline__ __half2 tanh_h2(__half2 x) {
    uint32_t r;
    asm("tanh.approx.f16x2 %0, %1;" : "=r"(r) : "r"(h2u(x)));
    return u2h(r);
}
__device__ __forceinline__ __half2 gelu_h2(__half2 x) {
    const __half2 c1 = __float2half2_rn(0.035677408136300125f);
    const __half2 c0 = __float2half2_rn(0.7978845608028654f);
    const __half2 hf = __float2half2_rn(0.5f);
    __half2 x2 = __hmul2(x, x);
    __half2 t  = __hmul2(x, __hfma2(c1, x2, c0));
    __half2 th = tanh_h2(t);
    __half2 hx = __hmul2(hf, x);
    return __hfma2(hx, th, hx);
}
__device__ __forceinline__ float geluf(float x) {   // fp32, for the epilogue
    float t = x * fmaf(0.035677408136300125f, x * x, 0.7978845608028654f);
    float th;
    asm("tanh.approx.f32 %0, %1;" : "=f"(th) : "f"(t));
    float hx = 0.5f * x;
    return fmaf(hx, th, hx);
}
__device__ __forceinline__ void ldmx4(uint32_t* r, uint32_t addr) {
    asm volatile("ldmatrix.sync.aligned.m8n8.x4.shared.b16 {%0,%1,%2,%3}, [%4];"
        : "=r"(r[0]), "=r"(r[1]), "=r"(r[2]), "=r"(r[3]) : "r"(addr));
}
__device__ __forceinline__ void mma16816(float* c, const uint32_t* a, uint32_t b0, uint32_t b1) {
    asm volatile("mma.sync.aligned.m16n8k16.row.col.f32.f16.f16.f32 "
        "{%0,%1,%2,%3}, {%4,%5,%6,%7}, {%8,%9}, {%0,%1,%2,%3};"
        : "+f"(c[0]), "+f"(c[1]), "+f"(c[2]), "+f"(c[3])
        : "r"(a[0]), "r"(a[1]), "r"(a[2]), "r"(a[3]), "r"(b0), "r"(b1));
}
__device__ __forceinline__ void cp_async16(uint32_t saddr, const void* gptr) {
    asm volatile("cp.async.cg.shared.global [%0], [%1], 16;" :: "r"(saddr), "l"(gptr));
}
#define CP_COMMIT() asm volatile("cp.async.commit_group;" ::: "memory")
#define CP_WAIT0()  asm volatile("cp.async.wait_group 0;" ::: "memory")

// ---------------- kernel 1: layer-1 constant table (fp16 pairs) ----------------
__global__ void precompute_A(const float* __restrict__ ref,
                             const float* __restrict__ W1,
                             const float* __restrict__ b1) {
    __shared__ float sref[NC][NR];
    __shared__ float sW1[HID][11];
    __shared__ float sb1[HID];
    int bs = blockIdx.x;
    const float* rp = ref + (size_t)bs * NC * NR;
    for (int i = threadIdx.x; i < NC * NR; i += 256) sref[i >> 6][i & 63] = rp[i];
    for (int i = threadIdx.x; i < HID * 11; i += 256) sW1[i / 11][i % 11] = W1[i];
    if (threadIdx.x < HID) sb1[threadIdx.x] = b1[threadIdx.x];
    __syncthreads();
    int h2 = threadIdx.x & 31;
    int rq = threadIdx.x >> 5;
    int h0 = 2 * h2, h1 = 2 * h2 + 1;
    float w00 = sW1[h0][0], w01 = sW1[h1][0];
    float bb0 = sb1[h0],    bb1 = sb1[h1];
    float wc0[8], wc1[8];
    #pragma unroll
    for (int c = 0; c < 8; c++) { wc0[c] = sW1[h0][3 + c]; wc1[c] = sW1[h1][3 + c]; }
    for (int r = rq * 8; r < rq * 8 + 8; r++) {
        float rc   = fmaf((float)r, 2.0f / 63.0f, -1.0f);
        float acc0 = fmaf(w00, rc, bb0);
        float acc1 = fmaf(w01, rc, bb1);
        #pragma unroll
        for (int c = 0; c < 8; c++) {
            float sv = sref[c][r];
            acc0 = fmaf(wc0[c], sv, acc0);
            acc1 = fmaf(wc1[c], sv, acc1);
        }
        g_Ah[((size_t)bs * NR + r) * 32 + h2] = packh2(acc0, acc1);
    }
}

// ---------------- kernel 1b: W2 -> fp16 pitch-144 tile (once, not per CTA) ----------------
__global__ void precompute_W2h(const float* __restrict__ W2) {
    for (int idx = threadIdx.x; idx < HID * 32; idx += 256) {
        int j = idx >> 5, k2 = idx & 31;
        g_W2h[j * 36 + k2] = packh2(W2[j * HID + 2 * k2], W2[j * HID + 2 * k2 + 1]);
    }
}

// ---------------- kernel 2: fp16 HMMA + cp.async gather + hoisted coord term ----------------
__global__ void __launch_bounds__(256, 2) mlp_mma_kernel(
    const float* __restrict__ pc,
    const int*   __restrict__ lookup,
    const int*   __restrict__ samp,
    const float* __restrict__ W1,
    const float* __restrict__ W2,
    const float* __restrict__ b2,
    const float* __restrict__ W3,
    const float* __restrict__ b3,
    float*       __restrict__ out)
{
    extern __shared__ __align__(16) char smem[];
    const uint32_t sbase = smem_u32(smem);
    const int tid  = threadIdx.x;
    const int lane = tid & 31;
    const int w    = tid >> 5;
    const int rg   = w & 3;             // MMA row group: rows 32rg..32rg+31
    const int ch   = w >> 2;            // MMA col half:  cols 32ch..32ch+31
    const int r    = tid & 127;         // final-phase pixel id
    const int half = tid >> 7;          // final-phase j-half

    const int tileb = blockIdx.x;       // 0..2047
    const int b     = tileb >> 9;
    const int n0    = (tileb & 511) * 128;

    int*   sidx  = (int*)  (smem + OFF_SIDX);
    uint2* spxy2 = (uint2*)(smem + OFF_SPXY);
    int*   sab   = (int*)  (smem + OFF_SAB);
    float* sb2   = (float*)(smem + OFF_B2);
    float* sW3   = (float*)(smem + OFF_W3);
    float* part  = (float*)(smem + OFF_PART);

    // ---- prologue phase A ----
    if (tid < 128) {
        float px = pc[n0 + tid];
        float py = pc[NPIX + n0 + tid];
        spxy2[tid] = make_uint2(packh2(px, px), packh2(py, py));
        int sub  = lookup[n0 + tid];
        sab[tid] = ((b << 6) + sub) << 11;   // uint32 index into g_Ah
    }
    // W2h tile: plain copy of pre-converted global (no per-CTA conversion)
    {
        const uint4* src = (const uint4*)g_W2h;
        for (int i = tid; i < HID * 36 / 4; i += 256)
            *(uint4*)(smem + OFF_W + i * 16) = src[i];
    }
    if (tid < HID) sb2[tid] = b2[tid];
    for (int i = tid; i < COUT * HID; i += 256) sW3[i] = W3[i];
    __syncthreads();

    // ---- prologue phase B: fused gather indices (sab + idx*32) ----
    for (int i = tid; i < 128 * NSAMP; i += 256) {
        int rr = i / NSAMP, ss = i % NSAMP;
        sidx[ss * 128 + rr] = sab[rr] + samp[(size_t)(n0 + rr) * NSAMP + ss] * 32;
    }

    // per-lane W1 coord weights as half2 (h = 2*lane, 2*lane+1)
    const int l2 = lane * 2;
    const __half2 w11h = u2h(packh2(W1[l2 * 11 + 1], W1[(l2 + 1) * 11 + 1]));
    const __half2 w12h = u2h(packh2(W1[l2 * 11 + 2], W1[(l2 + 1) * 11 + 2]));

    // W fragments resident in registers for all samples
    const uint32_t b_row  = (uint32_t)((lane & 7) + ((lane >> 4) & 1) * 8);
    const uint32_t b_coff = (uint32_t)(((lane >> 3) & 1) * 16);
    uint32_t Bf[2][4][4];
    #pragma unroll
    for (int nt = 0; nt < 2; nt++)
        #pragma unroll
        for (int ks = 0; ks < 4; ks++)
            ldmx4(Bf[nt][ks],
                  sbase + OFF_W + (uint32_t)(ch * 32 + nt * 16 + b_row) * 144 + b_coff + ks * 32);

    // per-warp epilogue biases in regs
    const int jq = ch * 32 + (lane & 3) * 2;
    float bj0[4], bj1[4];
    #pragma unroll
    for (int nti = 0; nti < 4; nti++) { bj0[nti] = sb2[jq + nti * 8]; bj1[nti] = sb2[jq + nti * 8 + 1]; }

    const uint32_t a_row  = (uint32_t)((lane & 7) + ((lane >> 3) & 1) * 8);
    const uint32_t a_coff = (uint32_t)(((lane >> 4) & 1) * 16);

    // ---- hoisted sample-invariant coord term: cc[p][lane], same thread writes & reads ----
    const int p0 = rg * 32 + ch * 16;    // this warp's build rows
    {
        char* ccb = smem + OFF_CC + lane * 4;
        #pragma unroll
        for (int t = 0; t < 16; t++) {
            int p = p0 + t;
            uint2 pxy = spxy2[p];
            __half2 cc = __hfma2(w11h, u2h(pxy.x), __hmul2(w12h, u2h(pxy.y)));
            *(uint32_t*)(ccb + p * 128) = h2u(cc);
        }
    }
    __syncthreads();   // sidx ready

    // ---- warp-local h1 build: cp.async stage -> finish ----
    const int sub_row  = lane >> 3;             // 0..3 (4 rows per pass)
    const int chunk16  = (lane & 7) * 16;       // 16B chunk within a 128B row
    const uint32_t raw_base = sbase + OFF_RAW + (uint32_t)w * 4096;

    auto issue_gather = [&](int s, int buf) {   // 4 x cp.async.16B per lane
        uint32_t dst = raw_base + (uint32_t)buf * 2048 + chunk16;
        const int* sidx_s = sidx + s * 128 + p0;
        #pragma unroll
        for (int q = 0; q < 4; q++) {
            int row = sub_row + q * 4;
            int gi  = sidx_s[row];              // 8-lane broadcast LDS.32
            cp_async16(dst + (uint32_t)row * 128,
                       (const char*)g_Ah + (size_t)gi * 4 + chunk16);
        }
        CP_COMMIT();
    };
    auto finish_h1 = [&](int buf, int aoff) {
        const char* rawp = smem + OFF_RAW + w * 4096 + buf * 2048 + lane * 4;
        const char* ccp  = smem + OFF_CC + lane * 4;
        char* abuf = smem + aoff + lane * 4;
        #pragma unroll
        for (int t = 0; t < 16; t++) {
            int p = p0 + t;
            uint32_t av = *(const uint32_t*)(rawp + t * 128);  // conflict-free LDS.32
            uint32_t cc = *(const uint32_t*)(ccp + p * 128);   // conflict-free LDS.32
            __half2 pre = __hadd2(u2h(cc), u2h(av));
            *(uint32_t*)(abuf + p * 144) = h2u(gelu_h2(pre));
        }
    };

    #define PAIR_BAR() asm volatile("bar.sync %0, 64;" :: "r"(rg + 1) : "memory")

    float h2acc[2][4][4];
    #pragma unroll
    for (int mt = 0; mt < 2; mt++)
        #pragma unroll
        for (int nti = 0; nti < 4; nti++)
            #pragma unroll
            for (int i = 0; i < 4; i++) h2acc[mt][nti][i] = 0.0f;

    issue_gather(0, 0);
    CP_WAIT0();
    finish_h1(0, OFF_A0);
    PAIR_BAR();

    for (int s = 0; s < NSAMP; s++) {
        const uint32_t abase = sbase + (s & 1 ? OFF_A1 : OFF_A0);

        // stage next sample's gather; L2 latency rides under MMA + epilogue
        if (s + 1 < NSAMP) issue_gather(s + 1, (s + 1) & 1);

        // ---- MMA: warp (rg,ch) computes rows 32rg..+31 x cols 32ch..+31 ----
        float c[2][4][4];
        #pragma unroll
        for (int mt = 0; mt < 2; mt++)
            #pragma unroll
            for (int nti = 0; nti < 4; nti++) {     // bias-init accumulators
                c[mt][nti][0] = bj0[nti];
                c[mt][nti][1] = bj1[nti];
                c[mt][nti][2] = bj0[nti];
                c[mt][nti][3] = bj1[nti];
            }

        #pragma unroll
        for (int mt = 0; mt < 2; mt++) {
            uint32_t arow = abase + (uint32_t)(rg * 32 + mt * 16 + a_row) * 144 + a_coff;
            #pragma unroll
            for (int ks = 0; ks < 4; ks++) {
                uint32_t af[4];
                ldmx4(af, arow + ks * 32);
                #pragma unroll
                for (int nt = 0; nt < 2; nt++) {
                    mma16816(c[mt][nt * 2 + 0], af, Bf[nt][ks][0], Bf[nt][ks][1]);
                    mma16816(c[mt][nt * 2 + 1], af, Bf[nt][ks][2], Bf[nt][ks][3]);
                }
            }
        }
        // epilogue: fp32 gelu, fp32 accumulate
        #pragma unroll
        for (int mt = 0; mt < 2; mt++)
            #pragma unroll
            for (int nti = 0; nti < 4; nti++) {
                h2acc[mt][nti][0] += geluf(c[mt][nti][0]);
                h2acc[mt][nti][1] += geluf(c[mt][nti][1]);
                h2acc[mt][nti][2] += geluf(c[mt][nti][2]);
                h2acc[mt][nti][3] += geluf(c[mt][nti][3]);
            }

        if (s + 1 < NSAMP) {
            CP_WAIT0();
            finish_h1((s + 1) & 1, (s + 1) & 1 ? OFF_A1 : OFF_A0);
        }
        PAIR_BAR();
    }
    __syncthreads();   // all warps done -> safe to reuse A region as h2m

    // ---- h2 mean -> smem [128][72] (reuses A region) ----
    float* h2m = (float*)(smem + OFF_A0);
    {
        const float inv = 1.0f / 12.0f;
        int r0  = rg * 32 + (lane >> 2);
        int col = ch * 32 + (lane & 3) * 2;
        #pragma unroll
        for (int mt = 0; mt < 2; mt++)
            #pragma unroll
            for (int nti = 0; nti < 4; nti++) {
                int row = r0 + mt * 16;
                *(float2*)(h2m + row * 72 + col + nti * 8) =
                    make_float2(h2acc[mt][nti][0] * inv, h2acc[mt][nti][1] * inv);
                *(float2*)(h2m + (row + 8) * 72 + col + nti * 8) =
                    make_float2(h2acc[mt][nti][2] * inv, h2acc[mt][nti][3] * inv);
            }
    }
    __syncthreads();

    // ---- layer 3 (mean folded): thread (r, half) covers j in [32*half, 32*half+32) ----
    {
        float pacc[COUT];
        #pragma unroll
        for (int c = 0; c < COUT; c++) pacc[c] = 0.0f;
        const float* hrow = h2m + r * 72 + half * 32;
        #pragma unroll
        for (int q = 0; q < 8; q++) {
            float4 h4 = *(const float4*)(hrow + q * 4);
            int j = half * 32 + q * 4;
            #pragma unroll
            for (int c = 0; c < COUT; c++) {
                const float* w3r = sW3 + c * HID + j;
                pacc[c] = fmaf(w3r[0], h4.x, pacc[c]);
                pacc[c] = fmaf(w3r[1], h4.y, pacc[c]);
                pacc[c] = fmaf(w3r[2], h4.z, pacc[c]);
                pacc[c] = fmaf(w3r[3], h4.w, pacc[c]);
            }
        }
        if (half == 1) {
            #pragma unroll
            for (int c = 0; c < COUT; c++) part[r * COUT + c] = pacc[c];
        }
        __syncthreads();
        if (half == 0) {
            size_t base = (size_t)b * COUT * NPIX + n0 + r;
            #pragma unroll
            for (int c = 0; c < COUT; c++)
                out[base + (size_t)c * NPIX] = pacc[c] + part[r * COUT + c] + __ldg(b3 + c);
        }
    }
}

// ---------------- launch ----------------
extern "C" void kernel_launch(void* const* d_in, const int* in_sizes, int n_in,
                              void* d_out, int out_size) {
    const float* ref    = (const float*)d_in[0];
    const float* pc     = (const float*)d_in[1];
    const int*   lookup = (const int*)d_in[2];
    const int*   samp   = (const int*)d_in[3];
    const float* W1     = (const float*)d_in[4];
    const float* b1     = (const float*)d_in[5];
    const float* W2     = (const float*)d_in[6];
    const float* b2     = (const float*)d_in[7];
    const float* W3     = (const float*)d_in[8];
    const float* b3     = (const float*)d_in[9];
    float* out = (float*)d_out;

    cudaFuncSetAttribute(mlp_mma_kernel, cudaFuncAttributeMaxDynamicSharedMemorySize, SMEM_TOTAL);

    precompute_A<<<NB * NS, 256>>>(ref, W1, b1);
    precompute_W2h<<<1, 256>>>(W2);
    mlp_mma_kernel<<<NB * (NPIX / 128), 256, SMEM_TOTAL>>>(
        pc, lookup, samp, W1, W2, b2, W3, b3, out);
}

// round 14
// speedup vs baseline: 1.0654x; 1.0085x over previous
#include <cuda_runtime.h>
#include <cuda_fp16.h>
#include <cstdint>

#define NB    4
#define NS    64
#define NC    8
#define NR    64
#define NPIX  65536
#define NSAMP 12
#define HID   64
#define COUT  8

typedef unsigned long long u64;

// ---------------- dynamic smem layout ----------------
#define OFF_A0    0            // 18432 (128 x 64 fp16, pitch 144)
#define OFF_A1    18432        // 18432   (A0+A1 = 36864 reused as h2m f32[128][72])
#define OFF_W     36864        // 64*144 = 9216
#define OFF_SIDX  46080        // int[12][128] = 6144 (fused g_Ah index)
#define OFF_SPXY  52224        // uint2[128] = 1024  ((px,px),(py,py) half2 pairs)
#define OFF_SAB   53248        // int[128] = 512
#define OFF_B2    53760        // f32[64] = 256
#define OFF_W3    54016        // f32[8][64] = 2048
#define OFF_PART  56576        // f32[128][8] = 4096
#define OFF_RAW   60672        // per-warp staging: 8 warps x 2 bufs x 2048B = 32768
#define OFF_CC    93440        // coord term: 128 rows x 32 lanes x 4B = 16384
#define SMEM_TOTAL 109824

// g_A as fp16 pairs: [bs(256)][r(64)][h2(32)] uint32 (half2 of h=2*h2, 2*h2+1)
__device__ __align__(16) uint32_t g_Ah[NB * NS * NR * (HID / 2)];
// W2 as fp16, pitch-144 row layout (ready for direct smem copy)
__device__ __align__(16) uint32_t g_W2h[HID * 36];

// ---------------- helpers ----------------
__device__ __forceinline__ uint32_t smem_u32(const void* p) {
    uint32_t a;
    asm("{ .reg .u64 t; cvta.to.shared.u64 t, %1; cvt.u32.u64 %0, t; }" : "=r"(a) : "l"(p));
    return a;
}
__device__ __forceinline__ uint32_t packh2(float a, float b) {   // lo=a, hi=b
    uint32_t r;
    asm("cvt.rn.f16x2.f32 %0, %2, %1;" : "=r"(r) : "f"(a), "f"(b));
    return r;
}
__device__ __forceinline__ __half2 u2h(uint32_t u) { __half2 h; *(uint32_t*)&h = u; return h; }
__device__ __forceinline__ uint32_t h2u(__half2 h) { return *(uint32_t*)&h; }
__device__ __forceinline__ __half2 tanh_h2(__half2 x) {
    uint32_t r;
    asm("tanh.approx.f16x2 %0, %1;" : "=r"(r) : "r"(h2u(x)));
    return u2h(r);
}
__device__ __forceinline__ __half2 gelu_h2(__half2 x) {
    const __half2 c1 = __float2half2_rn(0.035677408136300125f);
    const __half2 c0 = __float2half2_rn(0.7978845608028654f);
    const __half2 hf = __float2half2_rn(0.5f);
    __half2 x2 = __hmul2(x, x);
    __half2 t  = __hmul2(x, __hfma2(c1, x2, c0));
    __half2 th = tanh_h2(t);
    __half2 hx = __hmul2(hf, x);
    return __hfma2(hx, th, hx);
}
// packed-f32x2 gelu pair + packed accumulate; tanh stays scalar fp32
// (arithmetic identical to the scalar geluf path: same ops, same rounding)
__device__ __forceinline__ void gelu2_acc64(float x0, float x1, u64& acc,
                                            u64 C1P, u64 C0P, u64 HALFP) {
    u64 X, T, TH, HX, RES;
    float t0, t1, th0, th1;
    asm("mov.b64 %0, {%1,%2};" : "=l"(X) : "f"(x0), "f"(x1));
    asm("mul.rn.f32x2 %0, %1, %1;" : "=l"(T) : "l"(X));
    asm("fma.rn.f32x2 %0, %1, %2, %3;" : "=l"(T) : "l"(T), "l"(C1P), "l"(C0P));
    asm("mul.rn.f32x2 %0, %1, %2;" : "=l"(T) : "l"(T), "l"(X));
    asm("mov.b64 {%0,%1}, %2;" : "=f"(t0), "=f"(t1) : "l"(T));
    asm("tanh.approx.f32 %0, %1;" : "=f"(th0) : "f"(t0));
    asm("tanh.approx.f32 %0, %1;" : "=f"(th1) : "f"(t1));
    asm("mov.b64 %0, {%1,%2};" : "=l"(TH) : "f"(th0), "f"(th1));
    asm("mul.rn.f32x2 %0, %1, %2;" : "=l"(HX) : "l"(X), "l"(HALFP));
    asm("fma.rn.f32x2 %0, %1, %2, %3;" : "=l"(RES) : "l"(HX), "l"(TH), "l"(HX));
    asm("add.rn.f32x2 %0, %1, %2;" : "=l"(acc) : "l"(acc), "l"(RES));
}
__device__ __forceinline__ u64 packf2(float a, float b) {
    u64 p;
    asm("mov.b64 %0, {%1,%2};" : "=l"(p) : "f"(a), "f"(b));
    return p;
}
__device__ __forceinline__ void unpackf2(u64 p, float& a, float& b) {
    asm("mov.b64 {%0,%1}, %2;" : "=f"(a), "=f"(b) : "l"(p));
}
__device__ __forceinline__ void ldmx4(uint32_t* r, uint32_t addr) {
    asm volatile("ldmatrix.sync.aligned.m8n8.x4.shared.b16 {%0,%1,%2,%3}, [%4];"
        : "=r"(r[0]), "=r"(r[1]), "=r"(r[2]), "=r"(r[3]) : "r"(addr));
}
__device__ __forceinline__ void mma16816(float* c, const uint32_t* a, uint32_t b0, uint32_t b1) {
    asm volatile("mma.sync.aligned.m16n8k16.row.col.f32.f16.f16.f32 "
        "{%0,%1,%2,%3}, {%4,%5,%6,%7}, {%8,%9}, {%0,%1,%2,%3};"
        : "+f"(c[0]), "+f"(c[1]), "+f"(c[2]), "+f"(c[3])
        : "r"(a[0]), "r"(a[1]), "r"(a[2]), "r"(a[3]), "r"(b0), "r"(b1));
}
__device__ __forceinline__ void cp_async16(uint32_t saddr, const void* gptr) {
    asm volatile("cp.async.cg.shared.global [%0], [%1], 16;" :: "r"(saddr), "l"(gptr));
}
#define CP_COMMIT() asm volatile("cp.async.commit_group;" ::: "memory")
#define CP_WAIT0()  asm volatile("cp.async.wait_group 0;" ::: "memory")

// ---------------- kernel 1: layer-1 constant table (fp16 pairs) ----------------
__global__ void precompute_A(const float* __restrict__ ref,
                             const float* __restrict__ W1,
                             const float* __restrict__ b1) {
    __shared__ float sref[NC][NR];
    __shared__ float sW1[HID][11];
    __shared__ float sb1[HID];
    int bs = blockIdx.x;
    const float* rp = ref + (size_t)bs * NC * NR;
    for (int i = threadIdx.x; i < NC * NR; i += 256) sref[i >> 6][i & 63] = rp[i];
    for (int i = threadIdx.x; i < HID * 11; i += 256) sW1[i / 11][i % 11] = W1[i];
    if (threadIdx.x < HID) sb1[threadIdx.x] = b1[threadIdx.x];
    __syncthreads();
    int h2 = threadIdx.x & 31;
    int rq = threadIdx.x >> 5;
    int h0 = 2 * h2, h1 = 2 * h2 + 1;
    float w00 = sW1[h0][0], w01 = sW1[h1][0];
    float bb0 = sb1[h0],    bb1 = sb1[h1];
    float wc0[8], wc1[8];
    #pragma unroll
    for (int c = 0; c < 8; c++) { wc0[c] = sW1[h0][3 + c]; wc1[c] = sW1[h1][3 + c]; }
    for (int r = rq * 8; r < rq * 8 + 8; r++) {
        float rc   = fmaf((float)r, 2.0f / 63.0f, -1.0f);
        float acc0 = fmaf(w00, rc, bb0);
        float acc1 = fmaf(w01, rc, bb1);
        #pragma unroll
        for (int c = 0; c < 8; c++) {
            float sv = sref[c][r];
            acc0 = fmaf(wc0[c], sv, acc0);
            acc1 = fmaf(wc1[c], sv, acc1);
        }
        g_Ah[((size_t)bs * NR + r) * 32 + h2] = packh2(acc0, acc1);
    }
}

// ---------------- kernel 1b: W2 -> fp16 pitch-144 tile (once, not per CTA) ----------------
__global__ void precompute_W2h(const float* __restrict__ W2) {
    for (int idx = threadIdx.x; idx < HID * 32; idx += 256) {
        int j = idx >> 5, k2 = idx & 31;
        g_W2h[j * 36 + k2] = packh2(W2[j * HID + 2 * k2], W2[j * HID + 2 * k2 + 1]);
    }
}

// ---------------- kernel 2: fp16 HMMA + cp.async gather + f32x2 epilogue ----------------
__global__ void __launch_bounds__(256, 2) mlp_mma_kernel(
    const float* __restrict__ pc,
    const int*   __restrict__ lookup,
    const int*   __restrict__ samp,
    const float* __restrict__ W1,
    const float* __restrict__ W2,
    const float* __restrict__ b2,
    const float* __restrict__ W3,
    const float* __restrict__ b3,
    float*       __restrict__ out)
{
    extern __shared__ __align__(16) char smem[];
    const uint32_t sbase = smem_u32(smem);
    const int tid  = threadIdx.x;
    const int lane = tid & 31;
    const int w    = tid >> 5;
    const int rg   = w & 3;             // MMA row group: rows 32rg..32rg+31
    const int ch   = w >> 2;            // MMA col half:  cols 32ch..32ch+31
    const int r    = tid & 127;         // final-phase pixel id
    const int half = tid >> 7;          // final-phase j-half

    const int tileb = blockIdx.x;       // 0..2047
    const int b     = tileb >> 9;
    const int n0    = (tileb & 511) * 128;

    int*   sidx  = (int*)  (smem + OFF_SIDX);
    uint2* spxy2 = (uint2*)(smem + OFF_SPXY);
    int*   sab   = (int*)  (smem + OFF_SAB);
    float* sb2   = (float*)(smem + OFF_B2);
    float* sW3   = (float*)(smem + OFF_W3);
    float* part  = (float*)(smem + OFF_PART);

    // ---- prologue phase A ----
    if (tid < 128) {
        float px = pc[n0 + tid];
        float py = pc[NPIX + n0 + tid];
        spxy2[tid] = make_uint2(packh2(px, px), packh2(py, py));
        int sub  = lookup[n0 + tid];
        sab[tid] = ((b << 6) + sub) << 11;   // uint32 index into g_Ah
    }
    // W2h tile: plain copy of pre-converted global (no per-CTA conversion)
    {
        const uint4* src = (const uint4*)g_W2h;
        for (int i = tid; i < HID * 36 / 4; i += 256)
            *(uint4*)(smem + OFF_W + i * 16) = src[i];
    }
    if (tid < HID) sb2[tid] = b2[tid];
    for (int i = tid; i < COUT * HID; i += 256) sW3[i] = W3[i];
    __syncthreads();

    // ---- prologue phase B: fused gather indices (sab + idx*32) ----
    for (int i = tid; i < 128 * NSAMP; i += 256) {
        int rr = i / NSAMP, ss = i % NSAMP;
        sidx[ss * 128 + rr] = sab[rr] + samp[(size_t)(n0 + rr) * NSAMP + ss] * 32;
    }

    // per-lane W1 coord weights as half2 (h = 2*lane, 2*lane+1)
    const int l2 = lane * 2;
    const __half2 w11h = u2h(packh2(W1[l2 * 11 + 1], W1[(l2 + 1) * 11 + 1]));
    const __half2 w12h = u2h(packh2(W1[l2 * 11 + 2], W1[(l2 + 1) * 11 + 2]));

    // f32x2 gelu constants (packed pairs)
    const u64 C1P   = packf2(0.035677408136300125f, 0.035677408136300125f);
    const u64 C0P   = packf2(0.7978845608028654f,   0.7978845608028654f);
    const u64 HALFP = packf2(0.5f, 0.5f);

    // W fragments resident in registers for all samples
    const uint32_t b_row  = (uint32_t)((lane & 7) + ((lane >> 4) & 1) * 8);
    const uint32_t b_coff = (uint32_t)(((lane >> 3) & 1) * 16);
    uint32_t Bf[2][4][4];
    #pragma unroll
    for (int nt = 0; nt < 2; nt++)
        #pragma unroll
        for (int ks = 0; ks < 4; ks++)
            ldmx4(Bf[nt][ks],
                  sbase + OFF_W + (uint32_t)(ch * 32 + nt * 16 + b_row) * 144 + b_coff + ks * 32);

    // per-warp epilogue biases in regs
    const int jq = ch * 32 + (lane & 3) * 2;
    float bj0[4], bj1[4];
    #pragma unroll
    for (int nti = 0; nti < 4; nti++) { bj0[nti] = sb2[jq + nti * 8]; bj1[nti] = sb2[jq + nti * 8 + 1]; }

    const uint32_t a_row  = (uint32_t)((lane & 7) + ((lane >> 3) & 1) * 8);
    const uint32_t a_coff = (uint32_t)(((lane >> 4) & 1) * 16);

    // ---- hoisted sample-invariant coord term: cc[p][lane], same thread writes & reads ----
    const int p0 = rg * 32 + ch * 16;    // this warp's build rows
    {
        char* ccb = smem + OFF_CC + lane * 4;
        #pragma unroll
        for (int t = 0; t < 16; t++) {
            int p = p0 + t;
            uint2 pxy = spxy2[p];
            __half2 cc = __hfma2(w11h, u2h(pxy.x), __hmul2(w12h, u2h(pxy.y)));
            *(uint32_t*)(ccb + p * 128) = h2u(cc);
        }
    }
    __syncthreads();   // sidx ready

    // ---- warp-local h1 build: cp.async stage -> finish ----
    const int sub_row  = lane >> 3;             // 0..3 (4 rows per pass)
    const int chunk16  = (lane & 7) * 16;       // 16B chunk within a 128B row
    const uint32_t raw_base = sbase + OFF_RAW + (uint32_t)w * 4096;

    auto issue_gather = [&](int s, int buf) {   // 4 x cp.async.16B per lane
        uint32_t dst = raw_base + (uint32_t)buf * 2048 + chunk16;
        const int* sidx_s = sidx + s * 128 + p0;
        #pragma unroll
        for (int q = 0; q < 4; q++) {
            int row = sub_row + q * 4;
            int gi  = sidx_s[row];              // 8-lane broadcast LDS.32
            cp_async16(dst + (uint32_t)row * 128,
                       (const char*)g_Ah + (size_t)gi * 4 + chunk16);
        }
        CP_COMMIT();
    };
    auto finish_h1 = [&](int buf, int aoff) {
        const char* rawp = smem + OFF_RAW + w * 4096 + buf * 2048 + lane * 4;
        const char* ccp  = smem + OFF_CC + lane * 4;
        char* abuf = smem + aoff + lane * 4;
        #pragma unroll
        for (int t = 0; t < 16; t++) {
            int p = p0 + t;
            uint32_t av = *(const uint32_t*)(rawp + t * 128);  // conflict-free LDS.32
            uint32_t cc = *(const uint32_t*)(ccp + p * 128);   // conflict-free LDS.32
            __half2 pre = __hadd2(u2h(cc), u2h(av));
            *(uint32_t*)(abuf + p * 144) = h2u(gelu_h2(pre));
        }
    };

    #define PAIR_BAR() asm volatile("bar.sync %0, 64;" :: "r"(rg + 1) : "memory")

    // h2 accumulators as packed f32x2 pairs: [mt][nti][0]=(v0,v1), [1]=(v2,v3)
    u64 h2acc[2][4][2];
    #pragma unroll
    for (int mt = 0; mt < 2; mt++)
        #pragma unroll
        for (int nti = 0; nti < 4; nti++) {
            h2acc[mt][nti][0] = 0ull;
            h2acc[mt][nti][1] = 0ull;
        }

    issue_gather(0, 0);
    CP_WAIT0();
    finish_h1(0, OFF_A0);
    PAIR_BAR();

    for (int s = 0; s < NSAMP; s++) {
        const uint32_t abase = sbase + (s & 1 ? OFF_A1 : OFF_A0);

        // stage next sample's gather; L2 latency rides under MMA + epilogue
        if (s + 1 < NSAMP) issue_gather(s + 1, (s + 1) & 1);

        // ---- MMA: warp (rg,ch) computes rows 32rg..+31 x cols 32ch..+31 ----
        float c[2][4][4];
        #pragma unroll
        for (int mt = 0; mt < 2; mt++)
            #pragma unroll
            for (int nti = 0; nti < 4; nti++) {     // bias-init accumulators
                c[mt][nti][0] = bj0[nti];
                c[mt][nti][1] = bj1[nti];
                c[mt][nti][2] = bj0[nti];
                c[mt][nti][3] = bj1[nti];
            }

        #pragma unroll
        for (int mt = 0; mt < 2; mt++) {
            uint32_t arow = abase + (uint32_t)(rg * 32 + mt * 16 + a_row) * 144 + a_coff;
            #pragma unroll
            for (int ks = 0; ks < 4; ks++) {
                uint32_t af[4];
                ldmx4(af, arow + ks * 32);
                #pragma unroll
                for (int nt = 0; nt < 2; nt++) {
                    mma16816(c[mt][nt * 2 + 0], af, Bf[nt][ks][0], Bf[nt][ks][1]);
                    mma16816(c[mt][nt * 2 + 1], af, Bf[nt][ks][2], Bf[nt][ks][3]);
                }
            }
        }
        // epilogue: packed f32x2 gelu (scalar fp32 tanh), packed accumulate
        #pragma unroll
        for (int mt = 0; mt < 2; mt++)
            #pragma unroll
            for (int nti = 0; nti < 4; nti++) {
                gelu2_acc64(c[mt][nti][0], c[mt][nti][1], h2acc[mt][nti][0], C1P, C0P, HALFP);
                gelu2_acc64(c[mt][nti][2], c[mt][nti][3], h2acc[mt][nti][1], C1P, C0P, HALFP);
            }

        if (s + 1 < NSAMP) {
            CP_WAIT0();
            finish_h1((s + 1) & 1, (s + 1) & 1 ? OFF_A1 : OFF_A0);
        }
        PAIR_BAR();
    }
    __syncthreads();   // all warps done -> safe to reuse A region as h2m

    // ---- h2 mean -> smem [128][72] (reuses A region) ----
    float* h2m = (float*)(smem + OFF_A0);
    {
        const float inv = 1.0f / 12.0f;
        int r0  = rg * 32 + (lane >> 2);
        int col = ch * 32 + (lane & 3) * 2;
        #pragma unroll
        for (int mt = 0; mt < 2; mt++)
            #pragma unroll
            for (int nti = 0; nti < 4; nti++) {
                int row = r0 + mt * 16;
                float v0, v1, v2, v3;
                unpackf2(h2acc[mt][nti][0], v0, v1);
                unpackf2(h2acc[mt][nti][1], v2, v3);
                *(float2*)(h2m + row * 72 + col + nti * 8) =
                    make_float2(v0 * inv, v1 * inv);
                *(float2*)(h2m + (row + 8) * 72 + col + nti * 8) =
                    make_float2(v2 * inv, v3 * inv);
            }
    }
    __syncthreads();

    // ---- layer 3 (mean folded): thread (r, half) covers j in [32*half, 32*half+32) ----
    {
        float pacc[COUT];
        #pragma unroll
        for (int c = 0; c < COUT; c++) pacc[c] = 0.0f;
        const float* hrow = h2m + r * 72 + half * 32;
        #pragma unroll
        for (int q = 0; q < 8; q++) {
            float4 h4 = *(const float4*)(hrow + q * 4);
            int j = half * 32 + q * 4;
            #pragma unroll
            for (int c = 0; c < COUT; c++) {
                const float* w3r = sW3 + c * HID + j;
                pacc[c] = fmaf(w3r[0], h4.x, pacc[c]);
                pacc[c] = fmaf(w3r[1], h4.y, pacc[c]);
                pacc[c] = fmaf(w3r[2], h4.z, pacc[c]);
                pacc[c] = fmaf(w3r[3], h4.w, pacc[c]);
            }
        }
        if (half == 1) {
            #pragma unroll
            for (int c = 0; c < COUT; c++) part[r * COUT + c] = pacc[c];
        }
        __syncthreads();
        if (half == 0) {
            size_t base = (size_t)b * COUT * NPIX + n0 + r;
            #pragma unroll
            for (int c = 0; c < COUT; c++)
                out[base + (size_t)c * NPIX] = pacc[c] + part[r * COUT + c] + __ldg(b3 + c);
        }
    }
}

// ---------------- launch ----------------
extern "C" void kernel_launch(void* const* d_in, const int* in_sizes, int n_in,
                              void* d_out, int out_size) {
    const float* ref    = (const float*)d_in[0];
    const float* pc     = (const float*)d_in[1];
    const int*   lookup = (const int*)d_in[2];
    const int*   samp   = (const int*)d_in[3];
    const float* W1     = (const float*)d_in[4];
    const float* b1     = (const float*)d_in[5];
    const float* W2     = (const float*)d_in[6];
    const float* b2     = (const float*)d_in[7];
    const float* W3     = (const float*)d_in[8];
    const float* b3     = (const float*)d_in[9];
    float* out = (float*)d_out;

    cudaFuncSetAttribute(mlp_mma_kernel, cudaFuncAttributeMaxDynamicSharedMemorySize, SMEM_TOTAL);

    precompute_A<<<NB * NS, 256>>>(ref, W1, b1);
    precompute_W2h<<<1, 256>>>(W2);
    mlp_mma_kernel<<<NB * (NPIX / 128), 256, SMEM_TOTAL>>>(
        pc, lookup, samp, W1, W2, b2, W3, b3, out);
}